// round 1
// baseline (speedup 1.0000x reference)
#include <cuda_runtime.h>

// RoiPoolingConv: bilinear crop-resize of 256 ROIs from a [128,128,512] f32
// image to [14,14,512] each. One CTA per output pixel (roi, py, px); 128
// threads x float4 covers the 512 channels with fully coalesced loads/stores.

__global__ void __launch_bounds__(128)
roi_pool_kernel(const float* __restrict__ img,
                const int*   __restrict__ rois,
                float*       __restrict__ out,
                int pool, int H, int W, int C)
{
    const int blk = blockIdx.x;
    const int px  = blk % pool;
    int tmp       = blk / pool;
    const int py  = tmp % pool;
    const int r   = tmp / pool;

    // roi = (x, y, w, h)
    const int4 roi = __ldg(((const int4*)rois) + r);
    const int rx = roi.x, ry = roi.y, rw = roi.z, rh = roi.w;

    const float poolf = (float)pool;

    // ---- y axis: match reference fp32 rounding exactly ----
    // scale = h / pool ; src = (py + 0.5)*scale - 0.5 ; clip ; floor ; frac
    float hf     = (float)rh;
    float scaley = __fdiv_rn(hf, poolf);
    float sy     = __fsub_rn(__fmul_rn((float)py + 0.5f, scaley), 0.5f);
    sy = fminf(fmaxf(sy, 0.0f), hf - 1.0f);
    int   iy0 = (int)sy;                 // sy >= 0 so trunc == floor
    int   iy1 = min(iy0 + 1, rh - 1);
    float fy  = sy - (float)iy0;

    // ---- x axis ----
    float wf     = (float)rw;
    float scalex = __fdiv_rn(wf, poolf);
    float sx     = __fsub_rn(__fmul_rn((float)px + 0.5f, scalex), 0.5f);
    sx = fminf(fmaxf(sx, 0.0f), wf - 1.0f);
    int   ix0 = (int)sx;
    int   ix1 = min(ix0 + 1, rw - 1);
    float fx  = sx - (float)ix0;

    const int y0 = ry + iy0, y1 = ry + iy1;
    const int x0 = rx + ix0, x1 = rx + ix1;

    const int C4 = C >> 2;
    const float4* p00 = (const float4*)(img + (size_t)(y0 * W + x0) * C);
    const float4* p01 = (const float4*)(img + (size_t)(y0 * W + x1) * C);
    const float4* p10 = (const float4*)(img + (size_t)(y1 * W + x0) * C);
    const float4* p11 = (const float4*)(img + (size_t)(y1 * W + x1) * C);

    float4* o = (float4*)(out + (size_t)blk * C);

    const float gx = 1.0f - fx;
    const float gy = 1.0f - fy;

    for (int c = threadIdx.x; c < C4; c += blockDim.x) {
        float4 a = __ldg(p00 + c);
        float4 b = __ldg(p01 + c);
        float4 d = __ldg(p10 + c);
        float4 e = __ldg(p11 + c);

        float4 res;
        {
            float top = a.x * gx + b.x * fx;
            float bot = d.x * gx + e.x * fx;
            res.x = top * gy + bot * fy;
        }
        {
            float top = a.y * gx + b.y * fx;
            float bot = d.y * gx + e.y * fx;
            res.y = top * gy + bot * fy;
        }
        {
            float top = a.z * gx + b.z * fx;
            float bot = d.z * gx + e.z * fx;
            res.z = top * gy + bot * fy;
        }
        {
            float top = a.w * gx + b.w * fx;
            float bot = d.w * gx + e.w * fx;
            res.w = top * gy + bot * fy;
        }
        o[c] = res;
    }
}

extern "C" void kernel_launch(void* const* d_in, const int* in_sizes, int n_in,
                              void* d_out, int out_size)
{
    const float* img  = (const float*)d_in[0];
    const int*   rois = (const int*)d_in[1];
    float*       out  = (float*)d_out;

    const int H = 128, W = 128;
    const int C        = in_sizes[0] / (H * W);      // 512
    const int num_rois = in_sizes[1] / 4;            // 256

    // pool^2 = out_size / (num_rois * C)
    const int pp = out_size / (num_rois * C);
    int pool = 1;
    while (pool * pool < pp) pool++;                 // 14

    const int grid = num_rois * pool * pool;         // 50176
    roi_pool_kernel<<<grid, 128>>>(img, rois, out, pool, H, W, C);
}

// round 2
// speedup vs baseline: 1.4142x; 1.4142x over previous
#include <cuda_runtime.h>

// RoiPoolingConv, two-phase:
//   Phase 1: one thread per output pixel computes 4 corner offsets (float4
//            units) + 4 bilinear weights into __device__ scratch.
//   Phase 2: flat kernel, thread = (pixel, c4). 2 broadcast param loads,
//            4 coalesced LDG.128, 16 FFMA, 1 STG.128. Minimal ALU overhead.

#define MAXPIX 65536   // >= num_rois * pool^2 (256*196 = 50176)

__device__ int4   g_offs[MAXPIX];   // corner offsets in float4 units
__device__ float4 g_wgts[MAXPIX];   // w00, w01, w10, w11

__global__ void roi_precompute_kernel(const int* __restrict__ rois,
                                      int total_pix, int pool,
                                      int W, int C)
{
    int pix = blockIdx.x * blockDim.x + threadIdx.x;
    if (pix >= total_pix) return;

    const int pp = pool * pool;
    const int r  = pix / pp;
    const int rem = pix - r * pp;
    const int py = rem / pool;
    const int px = rem - py * pool;

    const int4 roi = __ldg(((const int4*)rois) + r);
    const int rx = roi.x, ry = roi.y, rw = roi.z, rh = roi.w;

    const float poolf = (float)pool;

    // y axis — fp32 ops must match reference bit-for-bit up to the floor
    float hf     = (float)rh;
    float scaley = __fdiv_rn(hf, poolf);
    float sy     = __fsub_rn(__fmul_rn((float)py + 0.5f, scaley), 0.5f);
    sy = fminf(fmaxf(sy, 0.0f), hf - 1.0f);
    int   iy0 = (int)sy;
    int   iy1 = min(iy0 + 1, rh - 1);
    float fy  = sy - (float)iy0;

    // x axis
    float wf     = (float)rw;
    float scalex = __fdiv_rn(wf, poolf);
    float sx     = __fsub_rn(__fmul_rn((float)px + 0.5f, scalex), 0.5f);
    sx = fminf(fmaxf(sx, 0.0f), wf - 1.0f);
    int   ix0 = (int)sx;
    int   ix1 = min(ix0 + 1, rw - 1);
    float fx  = sx - (float)ix0;

    const int y0 = ry + iy0, y1 = ry + iy1;
    const int x0 = rx + ix0, x1 = rx + ix1;
    const int C4 = C >> 2;

    int4 offs;
    offs.x = (y0 * W + x0) * C4;
    offs.y = (y0 * W + x1) * C4;
    offs.z = (y1 * W + x0) * C4;
    offs.w = (y1 * W + x1) * C4;

    const float gx = 1.0f - fx;
    const float gy = 1.0f - fy;
    float4 w;
    w.x = gx * gy;   // 00
    w.y = fx * gy;   // 01
    w.z = gx * fy;   // 10
    w.w = fx * fy;   // 11

    g_offs[pix] = offs;
    g_wgts[pix] = w;
}

__global__ void __launch_bounds__(256)
roi_gather_kernel(const float* __restrict__ img,
                  float*       __restrict__ out,
                  int n_threads)
{
    int gid = blockIdx.x * blockDim.x + threadIdx.x;
    if (gid >= n_threads) return;

    const int pix = gid >> 7;      // C4 = 128 threads per pixel
    const int c4  = gid & 127;

    const int4   offs = g_offs[pix];   // warp-uniform -> L1 broadcast
    const float4 w    = g_wgts[pix];

    const float4* img4 = (const float4*)img;
    float4 a = __ldg(img4 + offs.x + c4);
    float4 b = __ldg(img4 + offs.y + c4);
    float4 d = __ldg(img4 + offs.z + c4);
    float4 e = __ldg(img4 + offs.w + c4);

    float4 res;
    res.x = a.x * w.x + b.x * w.y + d.x * w.z + e.x * w.w;
    res.y = a.y * w.x + b.y * w.y + d.y * w.z + e.y * w.w;
    res.z = a.z * w.x + b.z * w.y + d.z * w.z + e.z * w.w;
    res.w = a.w * w.x + b.w * w.y + d.w * w.z + e.w * w.w;

    ((float4*)out)[gid] = res;
}

extern "C" void kernel_launch(void* const* d_in, const int* in_sizes, int n_in,
                              void* d_out, int out_size)
{
    const float* img  = (const float*)d_in[0];
    const int*   rois = (const int*)d_in[1];
    float*       out  = (float*)d_out;

    const int H = 128, W = 128;
    const int C        = in_sizes[0] / (H * W);      // 512
    const int num_rois = in_sizes[1] / 4;            // 256

    const int pp = out_size / (num_rois * C);
    int pool = 1;
    while (pool * pool < pp) pool++;                 // 14

    const int total_pix = num_rois * pool * pool;    // 50176

    roi_precompute_kernel<<<(total_pix + 255) / 256, 256>>>(
        rois, total_pix, pool, W, C);

    const int n_threads = total_pix * (C >> 2);      // 6.42M
    roi_gather_kernel<<<(n_threads + 255) / 256, 256>>>(img, out, n_threads);
}